// round 2
// baseline (speedup 1.0000x reference)
#include <cuda_runtime.h>
#include <cstdint>
#include <cstddef>

#define BB 1024
#define FF 4096
#define DD 32

#define ROWGROUPS 16     // 64 rows each
#define CHUNKS 16        // F chunks of 256
#define ROWS_PB 64       // rows per block (= per warp)
#define F_PB 256         // f per block
#define WARPS 8
#define F_PW 32          // f per warp
#define TILE_PAD 65      // 64 rows + 1 pad word -> conflict-free transpose
#define TILE_FLOATS (33*65)   // 2145 floats: holds 32x65 tile AND 64x33 red buffer
#define RED_SZ (64*33)

// global accumulators (atomically accumulated): s[row][d] and bias_term[row]
__device__ float g_s[(size_t)BB * DD];
__device__ float g_b[(size_t)BB];

// ---- zero the accumulators (33792 floats = 132 blocks x 256) ----
__global__ void __launch_bounds__(256)
fm_zero()
{
    const int idx = blockIdx.x * 256 + threadIdx.x;
    if (idx < BB * DD) g_s[idx] = 0.f;
    else               g_b[idx - BB * DD] = 0.f;
}

// dynamic smem layout (floats):
//   [0,     8192)  embed slice: 256 f x 32 d
//   [8192,  8448)  bias slice: 256 f
//   [8448,  ...)   8 warp-private tiles (each TILE_FLOATS), reused as reduction buffers
__global__ void __launch_bounds__(256, 2)
fm_main(const float* __restrict__ data,
        const float* __restrict__ embed,
        const float* __restrict__ bias)
{
    extern __shared__ float sm[];
    float* s_embed = sm;
    float* s_bias  = sm + 8192;
    float* s_tiles = sm + 8448;

    const int tid  = threadIdx.x;
    const int w    = tid >> 5;
    const int lane = tid & 31;
    const int rg   = blockIdx.x & 15;
    const int ck   = blockIdx.x >> 4;
    const int rowbase = rg * ROWS_PB;
    const int fblk    = ck * F_PB;

    // ---- cooperative load of embed slice (256x32 = 32KB) and bias slice ----
    {
        const float4* eg = reinterpret_cast<const float4*>(embed + (size_t)fblk * DD);
        float4* es = reinterpret_cast<float4*>(s_embed);
        #pragma unroll
        for (int k = 0; k < 8; k++)
            es[tid + k * 256] = eg[tid + k * 256];
        s_bias[tid] = bias[fblk + tid];
    }

    // ---- stage data tile (warp-private transpose: [f][row], pad 65) ----
    float* tile = s_tiles + w * TILE_FLOATS;
    {
        const int fw = fblk + w * F_PW;
        const int r0 = lane >> 3;        // 0..3
        const int fq = (lane & 7) << 2;  // 0,4,...,28
        #pragma unroll
        for (int rr = 0; rr < ROWS_PB; rr += 4) {
            const int row = rr + r0;
            const float4 v = *reinterpret_cast<const float4*>(
                data + (size_t)(rowbase + row) * FF + fw + fq);
            tile[(fq + 0) * TILE_PAD + row] = v.x;
            tile[(fq + 1) * TILE_PAD + row] = v.y;
            tile[(fq + 2) * TILE_PAD + row] = v.z;
            tile[(fq + 3) * TILE_PAD + row] = v.w;
        }
    }
    __syncthreads();

    // ---- main loop: f32x2 packed FMA, lane owns rows {lane, lane+32} ----
    unsigned long long accA[16], accB[16];  // (s[row][2dp], s[row][2dp+1]) pairs
    #pragma unroll
    for (int i = 0; i < 16; i++) { accA[i] = 0ull; accB[i] = 0ull; }
    float bacc0 = 0.f, bacc1 = 0.f;

    const float* ebase = s_embed + (w * F_PW) * DD;
    const float* bbase = s_bias + w * F_PW;

    #pragma unroll 4
    for (int fi = 0; fi < F_PW; fi++) {
        const float d0 = tile[fi * TILE_PAD + lane];
        const float d1 = tile[fi * TILE_PAD + lane + 32];
        unsigned long long dv0, dv1;
        asm("mov.b64 %0, {%1, %1};" : "=l"(dv0) : "f"(d0));
        asm("mov.b64 %0, {%1, %1};" : "=l"(dv1) : "f"(d1));
        const float bf = bbase[fi];
        bacc0 = fmaf(d0, bf, bacc0);
        bacc1 = fmaf(d1, bf, bacc1);
        // embed row: 8x LDS.128 (16B-aligned: row stride is 128B)
        const ulonglong2* ev =
            reinterpret_cast<const ulonglong2*>(ebase + fi * DD);
        #pragma unroll
        for (int dq = 0; dq < 8; dq++) {
            const ulonglong2 e = ev[dq];   // two f32x2 packs
            asm("fma.rn.f32x2 %0, %1, %2, %0;" : "+l"(accA[2*dq])   : "l"(dv0), "l"(e.x));
            asm("fma.rn.f32x2 %0, %1, %2, %0;" : "+l"(accA[2*dq+1]) : "l"(dv0), "l"(e.y));
            asm("fma.rn.f32x2 %0, %1, %2, %0;" : "+l"(accB[2*dq])   : "l"(dv1), "l"(e.x));
            asm("fma.rn.f32x2 %0, %1, %2, %0;" : "+l"(accB[2*dq+1]) : "l"(dv1), "l"(e.y));
        }
    }

    // ---- dump per-warp partials into own tile region: red[row*33 + d], d=32 bias ----
    {
        float* red = tile;
        #pragma unroll
        for (int dp = 0; dp < 16; dp++) {
            float a0, a1, b0, b1;
            asm("mov.b64 {%0, %1}, %2;" : "=f"(a0), "=f"(a1) : "l"(accA[dp]));
            asm("mov.b64 {%0, %1}, %2;" : "=f"(b0), "=f"(b1) : "l"(accB[dp]));
            red[lane * 33 + 2 * dp]            = a0;
            red[lane * 33 + 2 * dp + 1]        = a1;
            red[(lane + 32) * 33 + 2 * dp]     = b0;
            red[(lane + 32) * 33 + 2 * dp + 1] = b1;
        }
        red[lane * 33 + 32]        = bacc0;
        red[(lane + 32) * 33 + 32] = bacc1;
    }
    __syncthreads();

    // ---- block-level tree reduction across 8 warps, then REDG into accumulators ----
    for (int i = tid; i < RED_SZ; i += 256) {
        float s = 0.f;
        #pragma unroll
        for (int ww = 0; ww < WARPS; ww++)
            s += s_tiles[ww * TILE_FLOATS + i];
        const int row = i / 33;
        const int d   = i - row * 33;
        const int grow = rowbase + row;
        if (d < 32) atomicAdd(&g_s[(size_t)grow * DD + d], s);
        else        atomicAdd(&g_b[grow], s);
    }
}

// ---- finisher: warp per row over 132KB of accumulators; sigmoid ----
__global__ void __launch_bounds__(256)
fm_finish(const float* __restrict__ gbias, float* __restrict__ out)
{
    const int w    = threadIdx.x >> 5;
    const int lane = threadIdx.x & 31;
    const int row  = blockIdx.x * 8 + w;

    const float s = g_s[(size_t)row * DD + lane];   // coalesced 128B per warp
    float t = s * s;
    if (lane == 0)
        t += g_b[row];

    #pragma unroll
    for (int o = 16; o; o >>= 1)
        t += __shfl_xor_sync(0xffffffffu, t, o);

    if (lane == 0) {
        const float x = gbias[0] + t;
        out[row] = 1.0f / (1.0f + __expf(-x));
    }
}

extern "C" void kernel_launch(void* const* d_in, const int* in_sizes, int n_in,
                              void* d_out, int out_size)
{
    const float* data  = (const float*)d_in[0];
    const float* embed = (const float*)d_in[1];
    const float* bias  = (const float*)d_in[2];
    const float* gb    = (const float*)d_in[3];
    float* out = (float*)d_out;

    const int smem_bytes = (8192 + 256 + WARPS * TILE_FLOATS) * (int)sizeof(float);
    cudaFuncSetAttribute(fm_main, cudaFuncAttributeMaxDynamicSharedMemorySize, smem_bytes);

    fm_zero<<<(BB * DD + BB + 255) / 256, 256>>>();
    fm_main<<<ROWGROUPS * CHUNKS, 256, smem_bytes>>>(data, embed, bias);
    fm_finish<<<BB / 8, 256>>>(gb, out);
}

// round 4
// speedup vs baseline: 1.2937x; 1.2937x over previous
#include <cuda_runtime.h>
#include <cstdint>
#include <cstddef>

#define BB 1024
#define FF 4096
#define DD 32
#define NB 40            // GEMM N: 0-31 embed dims, 32 bias, 33-39 zero pad
#define NT 5             // n-tiles of 8
#define MTILES 8
#define KSPLITS 16
#define K_PER_CTA 256
#define KC 32            // K per chunk
#define NCHUNK 8         // chunks per CTA
#define A_STRIDE 36      // smem floats per A row (conflict-free, 16B aligned)
#define B_STRIDE 40      // smem floats per B k-row (conflict-free, 16B aligned)

__device__ float g_B2[(size_t)FF * NB];  // [k][n] weight matrix
__device__ float g_s[(size_t)BB * DD];   // accumulated s[row][d] (zero-init, self-zeroing)
__device__ float g_b[(size_t)BB];        // accumulated bias_term[row]

__device__ __forceinline__ uint32_t smem_u32(const void* p) {
    uint32_t a;
    asm("{ .reg .u64 t; cvta.to.shared.u64 t, %1; cvt.u32.u64 %0, t; }" : "=r"(a) : "l"(p));
    return a;
}
__device__ __forceinline__ void cp16(uint32_t dst, const void* src) {
    asm volatile("cp.async.ca.shared.global [%0], [%1], 16;" :: "r"(dst), "l"(src));
}
__device__ __forceinline__ void cp_commit() {
    asm volatile("cp.async.commit_group;");
}
template <int N>
__device__ __forceinline__ void cp_wait() {
    asm volatile("cp.async.wait_group %0;" :: "n"(N));
}

// ---------------- prep: g_B2[k][n] = [embed^T ; bias ; 0] ----------------
__global__ void __launch_bounds__(256)
fm_prep(const float* __restrict__ embed, const float* __restrict__ bias)
{
    __shared__ float s[256 * 33];
    const int t = threadIdx.x;
    const int kblock = blockIdx.x * 256;

    const float4* eg = reinterpret_cast<const float4*>(embed + (size_t)kblock * DD);
    #pragma unroll
    for (int i = 0; i < 8; i++) {
        const int idx = t + i * 256;       // float4 index in 256x32 tile
        const float4 v = eg[idx];
        const int k = idx >> 3, q = (idx & 7) << 2;
        s[k * 33 + q + 0] = v.x; s[k * 33 + q + 1] = v.y;
        s[k * 33 + q + 2] = v.z; s[k * 33 + q + 3] = v.w;
    }
    s[t * 33 + 32] = bias[kblock + t];
    __syncthreads();

    float* dst = g_B2 + (size_t)kblock * NB;
    #pragma unroll
    for (int i = 0; i < 40; i++) {
        const int idx = t + i * 256;       // coalesced float writes
        const int k = idx / NB, n = idx - k * NB;
        dst[idx] = (n < 33) ? s[k * 33 + n] : 0.f;
    }
}

// ---------------- GEMM: tf32 mma.sync, 2-stage cp.async pipeline ----------------
__global__ void __launch_bounds__(256, 1)
fm_gemm(const float* __restrict__ data)
{
    __shared__ float As[2][128 * A_STRIDE];   // 36 KB
    __shared__ float Bs[2][KC * B_STRIDE];    // 10 KB

    const int t = threadIdx.x;
    const int w = t >> 5, lane = t & 31;
    const int g = lane >> 2, ctg = lane & 3;
    const int mtile = blockIdx.x & 7;
    const int kbase = (blockIdx.x >> 3) * K_PER_CTA;
    const float* arow0 = data + (size_t)(mtile * 128) * FF + kbase;

    auto loadA = [&](int c, int buf) {
        #pragma unroll
        for (int i = 0; i < 4; i++) {
            const int idx = t + i * 256;           // 1024 float4
            const int row = idx >> 3, kq = (idx & 7) << 2;
            cp16(smem_u32(&As[buf][row * A_STRIDE + kq]),
                 arow0 + (size_t)row * FF + c * KC + kq);
        }
    };
    auto loadB = [&](int c, int buf) {
        const float* src = g_B2 + (size_t)(kbase + c * KC) * NB;  // 320 contiguous float4
        cp16(smem_u32(&Bs[buf][t * 4]), src + t * 4);
        if (t < 64)
            cp16(smem_u32(&Bs[buf][(t + 256) * 4]), src + (t + 256) * 4);
    };

    float acc[NT][4];
    #pragma unroll
    for (int nt = 0; nt < NT; nt++)
        #pragma unroll
        for (int j = 0; j < 4; j++) acc[nt][j] = 0.f;

    loadA(0, 0); loadB(0, 0); cp_commit();

    for (int ch = 0; ch < NCHUNK; ch++) {
        const int buf = ch & 1;
        if (ch + 1 < NCHUNK) {
            loadA(ch + 1, buf ^ 1); loadB(ch + 1, buf ^ 1); cp_commit();
            cp_wait<1>();
        } else {
            cp_wait<0>();
        }
        __syncthreads();

        const float* Aw = &As[buf][(w * 16) * A_STRIDE];
        const float* Bw = &Bs[buf][0];

        #pragma unroll
        for (int ks = 0; ks < 4; ks++) {
            const int k0 = ks * 8;
            const uint32_t a0 = __float_as_uint(Aw[g * A_STRIDE + k0 + ctg]);
            const uint32_t a1 = __float_as_uint(Aw[(g + 8) * A_STRIDE + k0 + ctg]);
            const uint32_t a2 = __float_as_uint(Aw[g * A_STRIDE + k0 + ctg + 4]);
            const uint32_t a3 = __float_as_uint(Aw[(g + 8) * A_STRIDE + k0 + ctg + 4]);
            #pragma unroll
            for (int nt = 0; nt < NT; nt++) {
                const uint32_t b0 = __float_as_uint(Bw[(k0 + ctg) * B_STRIDE + nt * 8 + g]);
                const uint32_t b1 = __float_as_uint(Bw[(k0 + ctg + 4) * B_STRIDE + nt * 8 + g]);
                asm volatile(
                    "mma.sync.aligned.m16n8k8.row.col.f32.tf32.tf32.f32 "
                    "{%0,%1,%2,%3}, {%4,%5,%6,%7}, {%8,%9}, {%0,%1,%2,%3};"
                    : "+f"(acc[nt][0]), "+f"(acc[nt][1]), "+f"(acc[nt][2]), "+f"(acc[nt][3])
                    : "r"(a0), "r"(a1), "r"(a2), "r"(a3), "r"(b0), "r"(b1));
            }
        }
        __syncthreads();
    }

    // epilogue: one atomic pass; cols 33..39 are exact zeros (discard)
    const int mbase = mtile * 128 + w * 16;
    #pragma unroll
    for (int nt = 0; nt < NT; nt++) {
        #pragma unroll
        for (int j = 0; j < 4; j++) {
            const int n = nt * 8 + 2 * ctg + (j & 1);
            const int m = mbase + g + ((j >> 1) << 3);
            if (n < DD)
                atomicAdd(&g_s[(size_t)m * DD + n], acc[nt][j]);
            else if (n == DD)
                atomicAdd(&g_b[m], acc[nt][j]);
        }
    }
}

// ---------------- finisher: sigmoid + self-zero accumulators ----------------
__global__ void __launch_bounds__(256)
fm_finish(const float* __restrict__ gbias, float* __restrict__ out)
{
    const int w = threadIdx.x >> 5, lane = threadIdx.x & 31;
    const int row = blockIdx.x * 8 + w;

    const float s = g_s[(size_t)row * DD + lane];
    float t = s * s;
    if (lane == 0) t += g_b[row];

    #pragma unroll
    for (int o = 16; o; o >>= 1)
        t += __shfl_xor_sync(0xffffffffu, t, o);

    if (lane == 0) {
        out[row] = 1.0f / (1.0f + __expf(-(gbias[0] + t)));
        g_b[row] = 0.f;
    }
    g_s[(size_t)row * DD + lane] = 0.f;   // reset for next replay
}

extern "C" void kernel_launch(void* const* d_in, const int* in_sizes, int n_in,
                              void* d_out, int out_size)
{
    const float* data  = (const float*)d_in[0];
    const float* embed = (const float*)d_in[1];
    const float* bias  = (const float*)d_in[2];
    const float* gb    = (const float*)d_in[3];
    float* out = (float*)d_out;

    fm_prep<<<FF / 256, 256>>>(embed, bias);
    fm_gemm<<<MTILES * KSPLITS, 256>>>(data);
    fm_finish<<<BB / 8, 256>>>(gb, out);
}